// round 9
// baseline (speedup 1.0000x reference)
#include <cuda_runtime.h>
#include <cstdint>

#define G    8
#define CG   32
#define CH   256
#define HWP  16384
#define TPB  1024
#define PT   64
#define XS   72        // padded floats per channel row in smem
#define NT   4096
#define SROW 9         // stats stride per pixel, in ull

typedef unsigned long long ull;

__device__ __forceinline__ ull pack2(float a, float b) {
    ull r; asm("mov.b64 %0, {%1,%2};" : "=l"(r) : "f"(a), "f"(b)); return r;
}
__device__ __forceinline__ void unpack2(ull v, float& a, float& b) {
    asm("mov.b64 {%0,%1}, %2;" : "=f"(a), "=f"(b) : "l"(v));
}
__device__ __forceinline__ void fma2(ull& d, ull a, ull b) {
    asm("fma.rn.f32x2 %0, %1, %2, %0;" : "+l"(d) : "l"(a), "l"(b));
}
__device__ __forceinline__ uint32_t smem_u32(const void* p) {
    uint32_t a;
    asm("{ .reg .u64 t; cvta.to.shared.u64 t, %1; cvt.u32.u64 %0, t; }" : "=r"(a) : "l"(p));
    return a;
}
__device__ __forceinline__ void cpa16(uint32_t dst, const float* src) {
    asm volatile("cp.async.cg.shared.global [%0], [%1], 16;" :: "r"(dst), "l"(src));
}

#define NEG_INF __int_as_float(0xff800000)

// smem layout (bytes)
#define XBYTES    (CH * XS * 4)             // 73728 per x buffer
#define OFF_W2    (2 * XBYTES)              // 147456, ull[CH*8] = 16KB
#define OFF_ST    (OFF_W2 + CH * 8 * 8)     // 163840
#define STB       (PT * SROW * 8)           // 4608 per stats buffer
#define OFF_W1    (OFF_ST + 2 * STB)        // 173056
#define OFF_TW1   (OFF_W1 + CH * 4)         // 174080
#define SMEM_SZ   (OFF_TW1 + 128)           // 174208

__global__ void __launch_bounds__(TPB, 1)
cgblock_kernel(const float* __restrict__ x,
               const float* __restrict__ soft_w1,
               const float* __restrict__ soft_w2,
               const float* __restrict__ top_w1,
               const float* __restrict__ top_w2,
               const float* __restrict__ rr,
               float* __restrict__ out)
{
    extern __shared__ char sm[];
    ull*   s_w2  = (ull*)(sm + OFF_W2);
    float* s_w1  = (float*)(sm + OFF_W1);
    float* s_tw1 = (float*)(sm + OFF_TW1);

    const int tid  = threadIdx.x;
    const int warp = tid >> 5;
    const int lane = tid & 31;

    // ---- one-time weight prep: w2[o*8+g] = (rs*soft_w2[o,g], rt*top_w2[o,g]) ----
    {
        float r0 = __ldg(rr), r1 = __ldg(rr + 1);
        float rm = fmaxf(r0, r1);
        float e0 = __expf(r0 - rm), e1 = __expf(r1 - rm);
        float inv = __frcp_rn(e0 + e1);
        float w_top = e0 * inv, w_soft = e1 * inv;
        #pragma unroll
        for (int i = tid; i < CH * G; i += TPB) {
            int o = i >> 3, g = i & 7;
            s_w2[i] = pack2(w_soft * __ldg(soft_w2 + o * G + g),
                            w_top  * __ldg(top_w2  + o * G + g));
        }
        if (tid < G * CG) s_w1[tid] = __ldg(soft_w1 + tid);
        if (tid < G * 4)  s_tw1[tid] = __ldg(top_w1 + tid);
    }
    __syncthreads();

    const uint32_t xbuf[2] = { smem_u32(sm), smem_u32(sm + XBYTES) };
    ull* s_st[2] = { (ull*)(sm + OFF_ST), (ull*)(sm + OFF_ST + STB) };

    // prefetch: thread -> (channel, 64B quarter of that channel's 256B row)
    const int ld_ch = tid >> 2;           // 0..255
    const int ld_q  = tid & 3;            // 0..3

    auto prefetch = [&](int t, int buf) {
        int p = t * PT, b = p >> 14, sp = p & (HWP - 1);
        const float* src = x + ((size_t)b * CH + ld_ch) * HWP + sp + ld_q * 16;
        uint32_t dst = xbuf[buf] + ld_ch * (XS * 4) + ld_q * 64;
        #pragma unroll
        for (int k2 = 0; k2 < 4; k2++) cpa16(dst + k2 * 16, src + k2 * 4);
        asm volatile("cp.async.commit_group;" ::: "memory");
    };

    // phase 1: two threads per (g,px); each scans 16 interleaved channels, shfl-merge.
    auto phase1 = [&](int buf, int sb) {
        const int g   = tid >> 7;         // 0..7
        const int rem = tid & 127;
        const int px  = rem >> 1;         // 0..63
        const int h   = rem & 1;          // channel-half
        const float* xt  = (const float*)(sm + (size_t)buf * XBYTES);
        const float* xr  = xt + (g * CG) * XS + px;
        const float* w1p = s_w1 + g * CG;

        float es = 0.f, ys = 0.f;
        float a0 = NEG_INF, b0 = NEG_INF, c0 = NEG_INF, d0 = NEG_INF;
        #pragma unroll
        for (int c = 0; c < 16; c++) {
            int coff = ((c >> 1) << 2) + (h << 1) + (c & 1);   // h=0: ch%4 in {0,1}; h=1: {2,3}
            float v  = xr[coff * XS];
            float w1 = w1p[coff];
            float e = __expf(v); es += e; ys = fmaf(v * e, w1, ys);
            float f  = fminf(a0, v); a0 = fmaxf(a0, v);
            float h2 = fminf(b0, f); b0 = fmaxf(b0, f);
            float i2 = fminf(c0, h2); c0 = fmaxf(c0, h2);
            d0 = fmaxf(d0, i2);
        }
        // in-warp merge of the two channel-halves (partner = lane^1)
        es += __shfl_xor_sync(0xffffffffu, es, 1);
        ys += __shfl_xor_sync(0xffffffffu, ys, 1);
        float pa = __shfl_xor_sync(0xffffffffu, a0, 1);
        float pb = __shfl_xor_sync(0xffffffffu, b0, 1);
        float pc = __shfl_xor_sync(0xffffffffu, c0, 1);
        float pd = __shfl_xor_sync(0xffffffffu, d0, 1);
        float m1 = fmaxf(a0, pd), m2 = fmaxf(b0, pc);
        float m3 = fmaxf(c0, pb), m4 = fmaxf(d0, pa);
        float r1 = fmaxf(m1, m3), r3 = fminf(m1, m3);
        float r2 = fmaxf(m2, m4), r4 = fminf(m2, m4);
        float A = fmaxf(r1, r2), B = fminf(r1, r2);
        float C = fmaxf(r3, r4), D = fminf(r3, r4);

        float k0 = s_tw1[g * 4 + 0], k1 = s_tw1[g * 4 + 1];
        float k2 = s_tw1[g * 4 + 2], k3 = s_tw1[g * 4 + 3];
        float sv = __fdividef(ys, es);
        float tv = fmaf(A, k0, fmaf(B, k1, fmaf(C, k2, D * k3)));
        if (h == 0) s_st[sb][px * SROW + g] = pack2(sv, tv);
    };

    // phase 2: warp -> 8 channels x 64 px (two sequential pixel-halves)
    auto phase2 = [&](int t, int buf, int sb) {
        const float* xt = (const float*)(sm + (size_t)buf * XBYTES);
        const ull* ps = s_st[sb];
        int p = t * PT, b = p >> 14, sp = p & (HWP - 1);
        float* ob = out + (size_t)b * CH * HWP + sp;
        const int cb = warp * 8;
        #pragma unroll
        for (int h = 0; h < 2; h++) {
            int p0 = h * 32 + lane;
            ull st8[8];
            #pragma unroll
            for (int g2 = 0; g2 < 8; g2++) st8[g2] = ps[p0 * SROW + g2];
            #pragma unroll
            for (int i = 0; i < 8; i++) {
                int o = cb + i;
                float xv = xt[o * XS + p0];
                ull acc = pack2(xv, 0.f);
                const ulonglong2* wo = (const ulonglong2*)(s_w2 + o * 8);
                #pragma unroll
                for (int gg = 0; gg < 4; gg++) {
                    ulonglong2 wv = wo[gg];
                    fma2(acc, st8[2 * gg],     wv.x);
                    fma2(acc, st8[2 * gg + 1], wv.y);
                }
                float lo, hi;
                unpack2(acc, lo, hi);
                __stcs(ob + (size_t)o * HWP + p0, lo + hi);
            }
        }
    };

    // ---- prologue ----
    const int S  = gridDim.x;
    const int t0 = blockIdx.x;

    prefetch(t0, 0);
    asm volatile("cp.async.wait_group 0;" ::: "memory");
    __syncthreads();
    phase1(0, 0);
    __syncthreads();

    // ---- main loop: prefetch(t+1) -> phase2(t) -> wait -> phase1(t+1) ----
    int i = 0;
    for (int t = t0; t < NT; t += S, i++) {
        int tn = t + S;
        int bp = i & 1;
        int sc = i & 1;
        if (tn < NT) prefetch(tn, bp ^ 1);
        phase2(t, bp, sc);
        asm volatile("cp.async.wait_group 0;" ::: "memory");
        __syncthreads();                   // x(t+1) visible; bp^1 owned by phase1
        if (tn < NT) phase1(bp ^ 1, sc ^ 1);
        __syncthreads();                   // stats(t+1) ready; bp free for prefetch
    }
}

extern "C" void kernel_launch(void* const* d_in, const int* in_sizes, int n_in,
                              void* d_out, int out_size) {
    const float* x   = (const float*)d_in[0];
    const float* sw1 = (const float*)d_in[1];
    const float* sw2 = (const float*)d_in[2];
    const float* tw1 = (const float*)d_in[3];
    const float* tw2 = (const float*)d_in[4];
    const float* r   = (const float*)d_in[5];
    float* out = (float*)d_out;

    static int sms = 0;
    if (sms == 0) cudaDeviceGetAttribute(&sms, cudaDevAttrMultiProcessorCount, 0);

    static bool attr_set = false;
    if (!attr_set) {
        cudaFuncSetAttribute(cgblock_kernel,
                             cudaFuncAttributeMaxDynamicSharedMemorySize, SMEM_SZ);
        attr_set = true;
    }

    cgblock_kernel<<<sms, TPB, SMEM_SZ>>>(x, sw1, sw2, tw1, tw2, r, out);
}

// round 10
// speedup vs baseline: 3.8096x; 3.8096x over previous
#include <cuda_runtime.h>
#include <cstdint>

#define G    8
#define CG   32
#define CH   256
#define HWP  16384
#define TPB  512
#define PT   64
#define XS   72        // padded floats per channel row in smem
#define NT   4096
#define SROW 9         // stats stride per pixel, in ull

typedef unsigned long long ull;

__device__ __forceinline__ ull pack2(float a, float b) {
    ull r; asm("mov.b64 %0, {%1,%2};" : "=l"(r) : "f"(a), "f"(b)); return r;
}
__device__ __forceinline__ void unpack2(ull v, float& a, float& b) {
    asm("mov.b64 {%0,%1}, %2;" : "=f"(a), "=f"(b) : "l"(v));
}
__device__ __forceinline__ void fma2(ull& d, ull a, ull b) {
    asm("fma.rn.f32x2 %0, %1, %2, %0;" : "+l"(d) : "l"(a), "l"(b));
}
__device__ __forceinline__ uint32_t smem_u32(const void* p) {
    uint32_t a;
    asm("{ .reg .u64 t; cvta.to.shared.u64 t, %1; cvt.u32.u64 %0, t; }" : "=r"(a) : "l"(p));
    return a;
}
__device__ __forceinline__ void cpa16(uint32_t dst, const float* src) {
    asm volatile("cp.async.cg.shared.global [%0], [%1], 16;" :: "r"(dst), "l"(src));
}

#define NEG_INF __int_as_float(0xff800000)

// smem layout (bytes)
#define XBYTES    (CH * XS * 4)             // 73728 per x buffer
#define OFF_W2    (2 * XBYTES)              // 147456, ull[CH*8] = 16KB
#define OFF_ST    (OFF_W2 + CH * 8 * 8)     // 163840
#define STB       (PT * SROW * 8)           // 4608 per stats buffer
#define OFF_W1    (OFF_ST + 2 * STB)        // 173056
#define OFF_TW1   (OFF_W1 + CH * 4)         // 174080
#define SMEM_SZ   (OFF_TW1 + 128)           // 174208

__global__ void __launch_bounds__(TPB, 1)
cgblock_kernel(const float* __restrict__ x,
               const float* __restrict__ soft_w1,
               const float* __restrict__ soft_w2,
               const float* __restrict__ top_w1,
               const float* __restrict__ top_w2,
               const float* __restrict__ rr,
               float* __restrict__ out)
{
    extern __shared__ char sm[];
    ull*   s_w2  = (ull*)(sm + OFF_W2);
    float* s_w1  = (float*)(sm + OFF_W1);
    float* s_tw1 = (float*)(sm + OFF_TW1);

    const int tid  = threadIdx.x;
    const int warp = tid >> 5;
    const int lane = tid & 31;

    // ---- one-time weight prep: w2[o*8+g] = (rs*soft_w2[o,g], rt*top_w2[o,g]) ----
    {
        float r0 = __ldg(rr), r1 = __ldg(rr + 1);
        float rm = fmaxf(r0, r1);
        float e0 = __expf(r0 - rm), e1 = __expf(r1 - rm);
        float inv = __frcp_rn(e0 + e1);
        float w_top = e0 * inv, w_soft = e1 * inv;
        #pragma unroll
        for (int i = tid; i < CH * G; i += TPB) {
            int o = i >> 3, g = i & 7;
            s_w2[i] = pack2(w_soft * __ldg(soft_w2 + o * G + g),
                            w_top  * __ldg(top_w2  + o * G + g));
        }
        if (tid < G * CG) s_w1[tid] = __ldg(soft_w1 + tid);
        if (tid < G * 4)  s_tw1[tid] = __ldg(top_w1 + tid);
    }
    __syncthreads();

    const uint32_t xbuf[2] = { smem_u32(sm), smem_u32(sm + XBYTES) };
    ull* s_st[2] = { (ull*)(sm + OFF_ST), (ull*)(sm + OFF_ST + STB) };

    // prefetch: thread -> (2 channels, 128B half of each 256B row)
    const int ld_ch = tid >> 1;           // 0..255
    const int ld_h  = tid & 1;            // 0..1

    auto prefetch = [&](int t, int buf) {
        int p = t * PT, b = p >> 14, sp = p & (HWP - 1);
        const float* src = x + ((size_t)b * CH + ld_ch) * HWP + sp + ld_h * 32;
        uint32_t dst = xbuf[buf] + ld_ch * (XS * 4) + ld_h * 128;
        #pragma unroll
        for (int k2 = 0; k2 < 8; k2++) cpa16(dst + k2 * 16, src + k2 * 4);
        asm volatile("cp.async.commit_group;" ::: "memory");
    };

    // phase 1: thread = (g, px); two independent chains over even/odd channels.
    auto phase1 = [&](int buf, int sb) {
        const int g  = tid >> 6;          // 0..7
        const int px = tid & 63;          // 0..63
        const float* xt  = (const float*)(sm + (size_t)buf * XBYTES);
        const float* xr  = xt + (g * CG) * XS + px;
        const float* w1p = s_w1 + g * CG;

        float es0 = 0.f, ys0 = 0.f, es1 = 0.f, ys1 = 0.f;
        float a0 = NEG_INF, b0 = NEG_INF, c0 = NEG_INF, d0 = NEG_INF;
        float a1 = NEG_INF, b1 = NEG_INF, c1 = NEG_INF, d1 = NEG_INF;

        #pragma unroll
        for (int c = 0; c < 16; c++) {
            float v0 = xr[(2 * c) * XS];
            float v1 = xr[(2 * c + 1) * XS];
            float w0 = w1p[2 * c];
            float w1 = w1p[2 * c + 1];
            {
                float e = __expf(v0); es0 += e; ys0 = fmaf(v0 * e, w0, ys0);
                float f  = fminf(a0, v0); a0 = fmaxf(a0, v0);
                float h2 = fminf(b0, f);  b0 = fmaxf(b0, f);
                float i2 = fminf(c0, h2); c0 = fmaxf(c0, h2);
                d0 = fmaxf(d0, i2);
            }
            {
                float e = __expf(v1); es1 += e; ys1 = fmaf(v1 * e, w1, ys1);
                float f  = fminf(a1, v1); a1 = fmaxf(a1, v1);
                float h2 = fminf(b1, f);  b1 = fmaxf(b1, f);
                float i2 = fminf(c1, h2); c1 = fmaxf(c1, h2);
                d1 = fmaxf(d1, i2);
            }
        }
        // merge the two sorted quads: top4(A ∪ B) via bitonic cleanup
        float m1 = fmaxf(a0, d1), m2 = fmaxf(b0, c1);
        float m3 = fmaxf(c0, b1), m4 = fmaxf(d0, a1);
        float r1 = fmaxf(m1, m3), r3 = fminf(m1, m3);
        float r2 = fmaxf(m2, m4), r4 = fminf(m2, m4);
        float A = fmaxf(r1, r2), B = fminf(r1, r2);
        float C = fmaxf(r3, r4), D = fminf(r3, r4);

        float k0 = s_tw1[g * 4 + 0], k1 = s_tw1[g * 4 + 1];
        float k2 = s_tw1[g * 4 + 2], k3 = s_tw1[g * 4 + 3];
        float sv = __fdividef(ys0 + ys1, es0 + es1);
        float tv = fmaf(A, k0, fmaf(B, k1, fmaf(C, k2, D * k3)));
        s_st[sb][px * SROW + g] = pack2(sv, tv);
    };

    // phase 2: warp -> 16 channels x 32 px-half (two sequential pixel-halves)
    auto phase2 = [&](int t, int buf, int sb) {
        const float* xt = (const float*)(sm + (size_t)buf * XBYTES);
        const ull* ps = s_st[sb];
        int p = t * PT, b = p >> 14, sp = p & (HWP - 1);
        float* ob = out + (size_t)b * CH * HWP + sp;
        const int cb = warp * 16;
        #pragma unroll
        for (int h = 0; h < 2; h++) {
            int p0 = h * 32 + lane;
            ull st8[8];
            #pragma unroll
            for (int g2 = 0; g2 < 8; g2++) st8[g2] = ps[p0 * SROW + g2];
            #pragma unroll 4
            for (int i = 0; i < 16; i++) {
                int o = cb + i;
                float xv = xt[o * XS + p0];
                ull acc = pack2(xv, 0.f);
                const ulonglong2* wo = (const ulonglong2*)(s_w2 + o * 8);
                #pragma unroll
                for (int gg = 0; gg < 4; gg++) {
                    ulonglong2 wv = wo[gg];
                    fma2(acc, st8[2 * gg],     wv.x);
                    fma2(acc, st8[2 * gg + 1], wv.y);
                }
                float lo, hi;
                unpack2(acc, lo, hi);
                __stcs(ob + (size_t)o * HWP + p0, lo + hi);
            }
        }
    };

    // ---- prologue ----
    const int S  = gridDim.x;
    const int t0 = blockIdx.x;

    prefetch(t0, 0);
    asm volatile("cp.async.wait_group 0;" ::: "memory");
    __syncthreads();
    phase1(0, 0);
    __syncthreads();

    // ---- main loop: prefetch(t+1) -> phase2(t) -> wait -> phase1(t+1) ----
    int i = 0;
    for (int t = t0; t < NT; t += S, i++) {
        int tn = t + S;
        int bp = i & 1;
        int sc = i & 1;
        if (tn < NT) prefetch(tn, bp ^ 1);
        phase2(t, bp, sc);
        asm volatile("cp.async.wait_group 0;" ::: "memory");
        __syncthreads();                   // x(t+1) visible
        if (tn < NT) phase1(bp ^ 1, sc ^ 1);
        __syncthreads();                   // stats(t+1) ready; bp free for prefetch
    }
}

extern "C" void kernel_launch(void* const* d_in, const int* in_sizes, int n_in,
                              void* d_out, int out_size) {
    const float* x   = (const float*)d_in[0];
    const float* sw1 = (const float*)d_in[1];
    const float* sw2 = (const float*)d_in[2];
    const float* tw1 = (const float*)d_in[3];
    const float* tw2 = (const float*)d_in[4];
    const float* r   = (const float*)d_in[5];
    float* out = (float*)d_out;

    static int sms = 0;
    if (sms == 0) cudaDeviceGetAttribute(&sms, cudaDevAttrMultiProcessorCount, 0);

    static bool attr_set = false;
    if (!attr_set) {
        cudaFuncSetAttribute(cgblock_kernel,
                             cudaFuncAttributeMaxDynamicSharedMemorySize, SMEM_SZ);
        attr_set = true;
    }

    cgblock_kernel<<<sms, TPB, SMEM_SZ>>>(x, sw1, sw2, tw1, tw2, r, out);
}

// round 11
// speedup vs baseline: 5.9942x; 1.5735x over previous
#include <cuda_runtime.h>
#include <cstdint>

#define G    8
#define CG   32
#define CH   256
#define HWP  16384
#define TPB  512
#define PT   64
#define NT   4096
#define SROW 9                      // stats stride per pixel, in ull

typedef unsigned long long ull;

__device__ __forceinline__ ull pack2(float a, float b) {
    ull r; asm("mov.b64 %0, {%1,%2};" : "=l"(r) : "f"(a), "f"(b)); return r;
}
__device__ __forceinline__ void unpack2(ull v, float& a, float& b) {
    asm("mov.b64 {%0,%1}, %2;" : "=f"(a), "=f"(b) : "l"(v));
}
__device__ __forceinline__ void fma2(ull& d, ull a, ull b) {
    asm("fma.rn.f32x2 %0, %1, %2, %0;" : "+l"(d) : "l"(a), "l"(b));
}
__device__ __forceinline__ uint32_t smem_u32(const void* p) {
    uint32_t a;
    asm("{ .reg .u64 t; cvta.to.shared.u64 t, %1; cvt.u32.u64 %0, t; }" : "=r"(a) : "l"(p));
    return a;
}
__device__ __forceinline__ void cpa16(uint32_t dst, const float* src) {
    asm volatile("cp.async.cg.shared.global [%0], [%1], 16;" :: "r"(dst), "l"(src));
}

#define NEG_INF __int_as_float(0xff800000)

// smem layout (bytes)  — identical to the 124.2us round-8 kernel
#define XBYTES    (CH * PT * 4)             // 65536 per buffer
#define OFF_W2    (3 * XBYTES)              // 196608, ull[CH*8] = 16KB
#define OFF_ST    (OFF_W2 + CH * 8 * 8)     // 212992
#define STBYTES   (PT * SROW * 8)           // 4608 per stats buffer
#define OFF_W1    (OFF_ST + 2 * STBYTES)    // 222208
#define OFF_TW1   (OFF_W1 + CH * 4)         // 223232
#define SMEM_SZ   (OFF_TW1 + 128)           // 223360

__global__ void __launch_bounds__(TPB, 1)
cgblock_kernel(const float* __restrict__ x,
               const float* __restrict__ soft_w1,
               const float* __restrict__ soft_w2,
               const float* __restrict__ top_w1,
               const float* __restrict__ top_w2,
               const float* __restrict__ rr,
               float* __restrict__ out)
{
    extern __shared__ char sm[];
    ull*   s_w2  = (ull*)(sm + OFF_W2);
    float* s_w1  = (float*)(sm + OFF_W1);
    float* s_tw1 = (float*)(sm + OFF_TW1);

    const int tid  = threadIdx.x;
    const int warp = tid >> 5;
    const int lane = tid & 31;

    // ---- one-time weight prep: w2[o*8+g] = (rs*soft_w2[o,g], rt*top_w2[o,g]) ----
    {
        float r0 = __ldg(rr), r1 = __ldg(rr + 1);
        float rm = fmaxf(r0, r1);
        float e0 = __expf(r0 - rm), e1 = __expf(r1 - rm);
        float inv = __frcp_rn(e0 + e1);
        float w_top = e0 * inv, w_soft = e1 * inv;
        #pragma unroll
        for (int i = tid; i < CH * G; i += TPB) {
            int o = i >> 3, g = i & 7;
            s_w2[i] = pack2(w_soft * __ldg(soft_w2 + o * G + g),
                            w_top  * __ldg(top_w2  + o * G + g));
        }
        if (tid < G * CG) s_w1[tid] = __ldg(soft_w1 + tid);
        if (tid < G * 4)  s_tw1[tid] = __ldg(top_w1 + tid);
    }
    __syncthreads();

    const uint32_t xbuf[3] = { smem_u32(sm), smem_u32(sm + XBYTES), smem_u32(sm + 2 * XBYTES) };
    ull* s_st[2] = { (ull*)(sm + OFF_ST), (ull*)(sm + OFF_ST + STBYTES) };

    // prefetch mapping: warp covers 2 contiguous channel rows (16 x 16B each)
    const int ld_ch  = tid >> 4;          // 0..31
    const int ld_off = (tid & 15) * 16;   // byte offset in 256B row

    auto prefetch = [&](int t, int buf) {
        int p = t * PT, b = p >> 14, sp = p & (HWP - 1);
        const float* src0 = x + (size_t)b * CH * HWP + sp + (ld_off >> 2);
        uint32_t dst0 = xbuf[buf] + ld_ch * 256 + ld_off;
        #pragma unroll
        for (int cc = 0; cc < 8; cc++)
            cpa16(dst0 + cc * (32 * 256), src0 + (size_t)(cc * 32 + ld_ch) * HWP);
        asm volatile("cp.async.commit_group;" ::: "memory");
    };

    // phase 1: thread = (g, px); TWO independent chains over even/odd channels,
    // merged with a register-only bitonic top-4 merge (exact).
    auto phase1 = [&](int buf, int sb) {
        const int g  = tid >> 6;          // 0..7
        const int px = tid & 63;          // 0..63
        const float* xt  = (const float*)(sm + (size_t)buf * XBYTES);
        const float* xr  = xt + (g * CG) * PT + px;
        const float* w1p = s_w1 + g * CG;

        float es0 = 0.f, ys0 = 0.f, es1 = 0.f, ys1 = 0.f;
        float a0 = NEG_INF, b0 = NEG_INF, c0 = NEG_INF, d0 = NEG_INF;
        float a1 = NEG_INF, b1 = NEG_INF, c1 = NEG_INF, d1 = NEG_INF;

        #pragma unroll
        for (int c = 0; c < 16; c++) {
            float v0 = xr[(2 * c) * PT];
            float v1 = xr[(2 * c + 1) * PT];
            float w0 = w1p[2 * c];
            float w1 = w1p[2 * c + 1];
            {
                float e = __expf(v0); es0 += e; ys0 = fmaf(v0 * e, w0, ys0);
                float f  = fminf(a0, v0); a0 = fmaxf(a0, v0);
                float h2 = fminf(b0, f);  b0 = fmaxf(b0, f);
                float i2 = fminf(c0, h2); c0 = fmaxf(c0, h2);
                d0 = fmaxf(d0, i2);
            }
            {
                float e = __expf(v1); es1 += e; ys1 = fmaf(v1 * e, w1, ys1);
                float f  = fminf(a1, v1); a1 = fmaxf(a1, v1);
                float h2 = fminf(b1, f);  b1 = fmaxf(b1, f);
                float i2 = fminf(c1, h2); c1 = fmaxf(c1, h2);
                d1 = fmaxf(d1, i2);
            }
        }
        // top4(A ∪ B): cross-max + bitonic cleanup (exact for sorted quads)
        float m1 = fmaxf(a0, d1), m2 = fmaxf(b0, c1);
        float m3 = fmaxf(c0, b1), m4 = fmaxf(d0, a1);
        float r1 = fmaxf(m1, m3), r3 = fminf(m1, m3);
        float r2 = fmaxf(m2, m4), r4 = fminf(m2, m4);
        float A = fmaxf(r1, r2), B = fminf(r1, r2);
        float C = fmaxf(r3, r4), D = fminf(r3, r4);

        float k0 = s_tw1[g * 4 + 0], k1 = s_tw1[g * 4 + 1];
        float k2 = s_tw1[g * 4 + 2], k3 = s_tw1[g * 4 + 3];
        float sv = __fdividef(ys0 + ys1, es0 + es1);
        float tv = fmaf(A, k0, fmaf(B, k1, fmaf(C, k2, D * k3)));
        s_st[sb][px * SROW + g] = pack2(sv, tv);
    };

    // phase 2: warp -> 16 channels x 2 pixel-halves (identical to round 8)
    auto phase2 = [&](int t, int buf, int sb) {
        ull st0[8], st1[8];
        const ull* ps = s_st[sb];
        #pragma unroll
        for (int g2 = 0; g2 < 8; g2++) {
            st0[g2] = ps[lane * SROW + g2];
            st1[g2] = ps[(lane + 32) * SROW + g2];
        }
        const float* xt = (const float*)(sm + (size_t)buf * XBYTES);
        int p = t * PT, b = p >> 14, sp = p & (HWP - 1);
        float* ob = out + (size_t)b * CH * HWP + sp;
        #pragma unroll 4
        for (int i = 0; i < 16; i++) {
            int o = warp * 16 + i;
            float x0 = xt[o * PT + lane];
            float x1 = xt[o * PT + 32 + lane];
            ull acc0 = pack2(x0, 0.f);
            ull acc1 = pack2(x1, 0.f);
            const ulonglong2* wo = (const ulonglong2*)(s_w2 + o * 8);
            #pragma unroll
            for (int gg = 0; gg < 4; gg++) {
                ulonglong2 wv = wo[gg];
                fma2(acc0, st0[2 * gg],     wv.x);
                fma2(acc1, st1[2 * gg],     wv.x);
                fma2(acc0, st0[2 * gg + 1], wv.y);
                fma2(acc1, st1[2 * gg + 1], wv.y);
            }
            float lo, hi;
            unpack2(acc0, lo, hi);
            __stcs(ob + (size_t)o * HWP + lane, lo + hi);
            unpack2(acc1, lo, hi);
            __stcs(ob + (size_t)o * HWP + 32 + lane, lo + hi);
        }
    };

    // ---- prologue (round-8 schedule: 2 prefetch groups in flight) ----
    const int S  = gridDim.x;
    const int t0 = blockIdx.x;

    prefetch(t0, 0);
    bool has1 = (t0 + S) < NT;
    if (has1) {
        prefetch(t0 + S, 1);
        asm volatile("cp.async.wait_group 1;" ::: "memory");
    } else {
        asm volatile("cp.async.wait_group 0;" ::: "memory");
    }
    __syncthreads();
    phase1(0, 0);
    __syncthreads();

    // ---- main loop: phase1(t+S) overlaps phase2(t) between barriers ----
    int i = 0;
    for (int t = t0; t < NT; t += S, i++) {
        int tn  = t + S;
        int tnn = t + 2 * S;
        int bufc = i % 3, bufn = (i + 1) % 3, bufp = (i + 2) % 3;
        int sc = i & 1, sn = sc ^ 1;

        if (tnn < NT) prefetch(tnn, bufp);
        if (tn < NT) {
            if (tnn < NT) { asm volatile("cp.async.wait_group 1;" ::: "memory"); }
            else          { asm volatile("cp.async.wait_group 0;" ::: "memory"); }
            __syncthreads();            // tile tn visible
            phase1(bufn, sn);           // stats for tn (no barrier before phase2)
        }
        phase2(t, bufc, sc);
        __syncthreads();                // stats(tn) done; bufc free for prefetch
    }
}

extern "C" void kernel_launch(void* const* d_in, const int* in_sizes, int n_in,
                              void* d_out, int out_size) {
    const float* x   = (const float*)d_in[0];
    const float* sw1 = (const float*)d_in[1];
    const float* sw2 = (const float*)d_in[2];
    const float* tw1 = (const float*)d_in[3];
    const float* tw2 = (const float*)d_in[4];
    const float* r   = (const float*)d_in[5];
    float* out = (float*)d_out;

    static int sms = 0;
    if (sms == 0) cudaDeviceGetAttribute(&sms, cudaDevAttrMultiProcessorCount, 0);

    static bool attr_set = false;
    if (!attr_set) {
        cudaFuncSetAttribute(cgblock_kernel,
                             cudaFuncAttributeMaxDynamicSharedMemorySize, SMEM_SZ);
        attr_set = true;
    }

    cgblock_kernel<<<sms, TPB, SMEM_SZ>>>(x, sw1, sw2, tw1, tw2, r, out);
}